// round 5
// baseline (speedup 1.0000x reference)
#include <cuda_runtime.h>
#include <cuda_bf16.h>
#include <cstdint>
#include <math.h>

#define Bn   8192
#define Dn   1024
#define HDn  128
#define BDsz ((size_t)Bn * (size_t)Dn)

#define THREADS 512

// smem layout (bytes)
#define A_HI_OFF   0            // 64 rows x 256B = 16KB
#define A_LO_OFF   16384
#define WBUF_OFF   32768        // two 64KB W buffers (hi 32KB + lo 32KB each)
#define SMEM_TOTAL 163840

// Pre-swizzled, transposed, hi/lo-split weight image: [gate][head][hi/lo][n=128][k=128]
// row = n (256 bytes of bf16 k), XOR-swizzled 16B chunks: phys_chunk = (k>>3) ^ (n&7)
__device__ __align__(16) __nv_bfloat16 g_Wimg[4][8][2][16384];

static __device__ __forceinline__ uint32_t smem_u32(const void* p) {
    uint32_t a;
    asm("{ .reg .u64 t; cvta.to.shared.u64 t, %1; cvt.u32.u64 %0, t; }" : "=r"(a) : "l"(p));
    return a;
}

#define LDMX4(r0, r1, r2, r3, addr)                                            \
    asm volatile("ldmatrix.sync.aligned.m8n8.x4.shared.b16 {%0,%1,%2,%3}, [%4];" \
                 : "=r"(r0), "=r"(r1), "=r"(r2), "=r"(r3) : "r"(addr))

#define MMA_BF16(d, a0, a1, a2, a3, b0, b1)                                    \
    asm volatile("mma.sync.aligned.m16n8k16.row.col.f32.bf16.bf16.f32 "        \
                 "{%0,%1,%2,%3},{%4,%5,%6,%7},{%8,%9},{%0,%1,%2,%3};"          \
                 : "+f"((d)[0]), "+f"((d)[1]), "+f"((d)[2]), "+f"((d)[3])      \
                 : "r"(a0), "r"(a1), "r"(a2), "r"(a3), "r"(b0), "r"(b1))

#define CP_ASYNC16(dst, src)                                                   \
    asm volatile("cp.async.cg.shared.global [%0], [%1], 16;" :: "r"(dst), "l"(src))

// ---------------------------------------------------------------------------
// Weight prep: W[h][d][e] (d=input, e=output) -> image[n=e][k=d], bf16 hi/lo
// split, XOR-swizzled 16B chunks within each 256B row.
// ---------------------------------------------------------------------------
__global__ void prep_w_kernel(const float* __restrict__ Wi, const float* __restrict__ Wf,
                              const float* __restrict__ Wz, const float* __restrict__ Wo) {
    int g = blockIdx.x >> 3;
    int hh = blockIdx.x & 7;
    const float* W = (g == 0 ? Wi : g == 1 ? Wf : g == 2 ? Wz : Wo) + hh * HDn * HDn;
    char* dhi = (char*)&g_Wimg[g][hh][0][0];
    char* dlo = (char*)&g_Wimg[g][hh][1][0];
    for (int idx = threadIdx.x; idx < HDn * HDn; idx += blockDim.x) {
        int n = idx >> 7;      // output col e
        int k = idx & 127;     // input dim d
        float w = W[k * HDn + n];
        __nv_bfloat16 hi = __float2bfloat16_rn(w);
        float rem = w - __bfloat162float(hi);
        __nv_bfloat16 lo = __float2bfloat16_rn(rem);
        int phys = ((((k >> 3) ^ (n & 7)) << 4) | ((k & 7) << 1));
        *(__nv_bfloat16*)(dhi + n * 256 + phys) = hi;
        *(__nv_bfloat16*)(dlo + n * 256 + phys) = lo;
    }
}

// ---------------------------------------------------------------------------
// Fused sLSTM kernel. CTA = 64 rows x one head (128 cols). 16 warps: 4 row x
// 4 col, each warp m16 x n32. Split-bf16 mma.sync GEMM (3 passes) for all 4
// gates into registers, then fragment-resident elementwise epilogue.
// ---------------------------------------------------------------------------
__global__ void __launch_bounds__(THREADS, 1) slstm_main(
    const float* __restrict__ gi, const float* __restrict__ gf,
    const float* __restrict__ gz, const float* __restrict__ go,
    const float* __restrict__ gc, const float* __restrict__ gn,
    const float* __restrict__ gm, const float* __restrict__ gh,
    const float* __restrict__ b_i, const float* __restrict__ b_f,
    const float* __restrict__ b_z, const float* __restrict__ b_o,
    float* __restrict__ out) {
    extern __shared__ char smem[];
    const int tid = threadIdx.x;
    const int wid = tid >> 5;
    const int lane = tid & 31;
    const int head = blockIdx.x & 7;
    const int row0 = (blockIdx.x >> 3) << 6;   // 64-row tile
    const int wr = wid & 3;                    // warp row (16 rows)
    const int wc = wid >> 2;                   // warp col (32 cols)
    const uint32_t sb = smem_u32(smem);

    // --- A tile: load h, split bf16 hi/lo, swizzled store ---
    {
        const float* hsrc = gh + (size_t)row0 * Dn + head * HDn;
        for (int t = tid; t < 64 * 32; t += THREADS) {
            int row = t >> 5;
            int k4 = t & 31;                   // group of 4 floats
            float4 v = *(const float4*)(hsrc + (size_t)row * Dn + (k4 << 2));
            __nv_bfloat16 a0 = __float2bfloat16_rn(v.x);
            __nv_bfloat16 a1 = __float2bfloat16_rn(v.y);
            __nv_bfloat16 a2 = __float2bfloat16_rn(v.z);
            __nv_bfloat16 a3 = __float2bfloat16_rn(v.w);
            __nv_bfloat16 l0 = __float2bfloat16_rn(v.x - __bfloat162float(a0));
            __nv_bfloat16 l1 = __float2bfloat16_rn(v.y - __bfloat162float(a1));
            __nv_bfloat16 l2 = __float2bfloat16_rn(v.z - __bfloat162float(a2));
            __nv_bfloat16 l3 = __float2bfloat16_rn(v.w - __bfloat162float(a3));
            uint32_t hi01 = (uint32_t)__bfloat16_as_ushort(a0) | ((uint32_t)__bfloat16_as_ushort(a1) << 16);
            uint32_t hi23 = (uint32_t)__bfloat16_as_ushort(a2) | ((uint32_t)__bfloat16_as_ushort(a3) << 16);
            uint32_t lo01 = (uint32_t)__bfloat16_as_ushort(l0) | ((uint32_t)__bfloat16_as_ushort(l1) << 16);
            uint32_t lo23 = (uint32_t)__bfloat16_as_ushort(l2) | ((uint32_t)__bfloat16_as_ushort(l3) << 16);
            int phys = ((((k4 >> 1) ^ (row & 7)) << 4) | ((k4 & 1) << 3));
            *(uint2*)(smem + A_HI_OFF + row * 256 + phys) = make_uint2(hi01, hi23);
            *(uint2*)(smem + A_LO_OFF + row * 256 + phys) = make_uint2(lo01, lo23);
        }
    }
    // --- preload W gate 0 via cp.async (image pre-swizzled: linear copy) ---
    {
        const char* src = (const char*)&g_Wimg[0][head][0][0];
        uint32_t dst = sb + WBUF_OFF;
        for (int t = tid; t < 4096; t += THREADS)
            CP_ASYNC16(dst + t * 16, src + t * 16);
        asm volatile("cp.async.commit_group;");
        asm volatile("cp.async.wait_group 0;");
    }
    __syncthreads();

    float ac[4][16];   // [gate][ntile*4 + j]
#pragma unroll
    for (int g = 0; g < 4; ++g)
#pragma unroll
        for (int j = 0; j < 16; ++j) ac[g][j] = 0.0f;

    // Precomputed ldmatrix lane addressing (byte offsets, swizzle applied per kt)
    const int a_row = (wr << 4) + (lane & 15);
    const int a_half = lane >> 4;                         // k half (8 elems)
    const int b_n0 = (wc << 5) + (lane & 7) + ((lane >> 4) << 3);
    const int b_half = (lane >> 3) & 1;

#pragma unroll
    for (int g = 0; g < 4; ++g) {
        const uint32_t wb = sb + WBUF_OFF + (uint32_t)(g & 1) * 65536u;
        if (g < 3) {
            const char* src = (const char*)&g_Wimg[g + 1][head][0][0];
            uint32_t dst = sb + WBUF_OFF + (uint32_t)((g + 1) & 1) * 65536u;
            for (int t = tid; t < 4096; t += THREADS)
                CP_ASYNC16(dst + t * 16, src + t * 16);
            asm volatile("cp.async.commit_group;");
        }
#pragma unroll
        for (int p = 0; p < 3; ++p) {
            const uint32_t abase = sb + ((p == 2) ? A_LO_OFF : A_HI_OFF) + a_row * 256;
            const uint32_t bbase = wb + ((p == 1) ? 32768u : 0u);
#pragma unroll
            for (int kt = 0; kt < 8; ++kt) {
                uint32_t a0, a1, a2, a3;
                {
                    int chunk = (kt << 1) + a_half;
                    uint32_t aaddr = abase + (((chunk ^ (a_row & 7)) & 15) << 4);
                    LDMX4(a0, a1, a2, a3, aaddr);
                }
                uint32_t b0, b1, b2, b3, b4, b5, b6, b7;
                {
                    int chunk = (kt << 1) + b_half;
                    int n0 = b_n0;
                    uint32_t baddr0 = bbase + n0 * 256 + (((chunk ^ (n0 & 7)) & 15) << 4);
                    int n1 = b_n0 + 16;
                    uint32_t baddr1 = bbase + n1 * 256 + (((chunk ^ (n1 & 7)) & 15) << 4);
                    LDMX4(b0, b1, b2, b3, baddr0);
                    LDMX4(b4, b5, b6, b7, baddr1);
                }
                MMA_BF16(ac[g] + 0,  a0, a1, a2, a3, b0, b1);
                MMA_BF16(ac[g] + 4,  a0, a1, a2, a3, b2, b3);
                MMA_BF16(ac[g] + 8,  a0, a1, a2, a3, b4, b5);
                MMA_BF16(ac[g] + 12, a0, a1, a2, a3, b6, b7);
            }
        }
        if (g < 3) {
            asm volatile("cp.async.wait_group 0;");
            __syncthreads();
        }
    }

    // --- epilogue directly on fragments ---
    // accum j = rs*2 + e : row = wr*16 + (lane>>2) + rs*8, col = wc*32 + nt*8 + (lane&3)*2 + e
    const int g0 = lane >> 2;
    const int cq = lane & 3;
#pragma unroll
    for (int rs = 0; rs < 2; ++rs) {
        const int row = row0 + (wr << 4) + g0 + (rs << 3);
#pragma unroll
        for (int nt = 0; nt < 4; ++nt) {
            const int col = head * HDn + (wc << 5) + (nt << 3) + (cq << 1);
            const size_t idx = (size_t)row * Dn + col;
            const float2 vbi = *(const float2*)(b_i + col);
            const float2 vbf = *(const float2*)(b_f + col);
            const float2 vbz = *(const float2*)(b_z + col);
            const float2 vbo = *(const float2*)(b_o + col);
            const float2 vi = *(const float2*)(gi + idx);
            const float2 vf = *(const float2*)(gf + idx);
            const float2 vz = *(const float2*)(gz + idx);
            const float2 vo = *(const float2*)(go + idx);
            const float2 vc = *(const float2*)(gc + idx);
            const float2 vn = *(const float2*)(gn + idx);
            const float2 vm = *(const float2*)(gm + idx);
            float2 oc, on, om, oh;
#pragma unroll
            for (int e = 0; e < 2; ++e) {
                const float pre_i = ac[0][nt * 4 + rs * 2 + e];
                const float pre_f = ac[1][nt * 4 + rs * 2 + e];
                const float pre_z = ac[2][nt * 4 + rs * 2 + e];
                const float pre_o = ac[3][nt * 4 + rs * 2 + e];
                const float ip = (e ? vi.y : vi.x) + pre_i + (e ? vbi.y : vbi.x);
                const float fp = (e ? vf.y : vf.x) + pre_f + (e ? vbf.y : vbf.x);
                const float zp = (e ? vz.y : vz.x) + pre_z + (e ? vbz.y : vbz.x);
                const float op = (e ? vo.y : vo.x) + pre_o + (e ? vbo.y : vbo.x);
                const float cv = e ? vc.y : vc.x;
                const float nv = e ? vn.y : vn.x;
                const float mv = e ? vm.y : vm.x;
                const float osig = 1.0f / (1.0f + __expf(-op));
                const float lf = fminf(fp, 0.0f) - log1pf(__expf(-fabsf(fp)));
                const float mn = fmaxf(lf + mv, ip);
                const float i_p = fminf(__expf(ip - mn), 1.0f);
                const float f_p = fminf(__expf(lf + mv - mn), 1.0f);
                const float cn = f_p * cv + i_p * tanhf(zp);
                const float nn = f_p * nv + i_p;
                const float hn = osig * (cn / fmaxf(nn, 1e-6f));
                if (e) { oc.y = cn; on.y = nn; om.y = mn; oh.y = hn; }
                else   { oc.x = cn; on.x = nn; om.x = mn; oh.x = hn; }
            }
            *(float2*)(out + idx) = oc;
            *(float2*)(out + BDsz + idx) = on;
            *(float2*)(out + 2 * BDsz + idx) = om;
            *(float2*)(out + 3 * BDsz + idx) = oh;
        }
    }
}

extern "C" void kernel_launch(void* const* d_in, const int* in_sizes, int n_in,
                              void* d_out, int out_size) {
    (void)in_sizes; (void)n_in; (void)out_size;
    // setup_inputs() dict insertion order: i, f, z, o, c, m, h, n, Wi, Wf, Wz, Wo, bi, bf, bz, bo
    const float* i_ = (const float*)d_in[0];
    const float* f_ = (const float*)d_in[1];
    const float* z_ = (const float*)d_in[2];
    const float* o_ = (const float*)d_in[3];
    const float* c_ = (const float*)d_in[4];
    const float* m_ = (const float*)d_in[5];
    const float* h_ = (const float*)d_in[6];
    const float* n_ = (const float*)d_in[7];
    const float* Wi = (const float*)d_in[8];
    const float* Wf = (const float*)d_in[9];
    const float* Wz = (const float*)d_in[10];
    const float* Wo = (const float*)d_in[11];
    const float* bi = (const float*)d_in[12];
    const float* bf = (const float*)d_in[13];
    const float* bz = (const float*)d_in[14];
    const float* bo = (const float*)d_in[15];
    float* out = (float*)d_out;

    cudaFuncSetAttribute(slstm_main, cudaFuncAttributeMaxDynamicSharedMemorySize, SMEM_TOTAL);

    prep_w_kernel<<<32, 256>>>(Wi, Wf, Wz, Wo);
    slstm_main<<<1024, THREADS, SMEM_TOTAL>>>(i_, f_, z_, o_, c_, n_, m_, h_,
                                              bi, bf, bz, bo, out);
}

// round 6
// speedup vs baseline: 1.2074x; 1.2074x over previous
#include <cuda_runtime.h>
#include <cuda_bf16.h>
#include <cstdint>
#include <math.h>

#define Bn   8192
#define Dn   1024
#define HDn  128
#define BDsz ((size_t)Bn * (size_t)Dn)

#define THREADS 512

// smem layout (bytes)
#define A_HI_OFF   0            // 64 rows x 256B = 16KB
#define A_LO_OFF   16384
#define WBUF_OFF   32768        // two 64KB W buffers (hi 32KB + lo 32KB each)
#define SMEM_TOTAL 163840
// After GEMM the whole smem is reused as the preact store:
// 4 gates x 64 rows x 132 floats (padded) = 135168 bytes < SMEM_TOTAL
#define PRE_STRIDE 132

// Pre-swizzled, transposed, hi/lo-split weight image: [gate][head][hi/lo][n=128][k=128]
// row = n (256 bytes of bf16 k), XOR-swizzled 16B chunks: phys_chunk = (k>>3) ^ (n&7)
__device__ __align__(16) __nv_bfloat16 g_Wimg[4][8][2][16384];

static __device__ __forceinline__ uint32_t smem_u32(const void* p) {
    uint32_t a;
    asm("{ .reg .u64 t; cvta.to.shared.u64 t, %1; cvt.u32.u64 %0, t; }" : "=r"(a) : "l"(p));
    return a;
}

#define LDMX4(r0, r1, r2, r3, addr)                                            \
    asm volatile("ldmatrix.sync.aligned.m8n8.x4.shared.b16 {%0,%1,%2,%3}, [%4];" \
                 : "=r"(r0), "=r"(r1), "=r"(r2), "=r"(r3) : "r"(addr))

#define MMA_BF16(d, a0, a1, a2, a3, b0, b1)                                    \
    asm volatile("mma.sync.aligned.m16n8k16.row.col.f32.bf16.bf16.f32 "        \
                 "{%0,%1,%2,%3},{%4,%5,%6,%7},{%8,%9},{%0,%1,%2,%3};"          \
                 : "+f"((d)[0]), "+f"((d)[1]), "+f"((d)[2]), "+f"((d)[3])      \
                 : "r"(a0), "r"(a1), "r"(a2), "r"(a3), "r"(b0), "r"(b1))

#define CP_ASYNC16(dst, src)                                                   \
    asm volatile("cp.async.cg.shared.global [%0], [%1], 16;" :: "r"(dst), "l"(src))

// ---------------------------------------------------------------------------
// Weight prep: W[h][d][e] (d=input, e=output) -> image[n=e][k=d], bf16 hi/lo
// split, XOR-swizzled 16B chunks within each 256B row. 256 CTAs (n-sliced).
// ---------------------------------------------------------------------------
__global__ void prep_w_kernel(const float* __restrict__ Wi, const float* __restrict__ Wf,
                              const float* __restrict__ Wz, const float* __restrict__ Wo) {
    int g  = blockIdx.x >> 6;
    int hh = (blockIdx.x >> 3) & 7;
    int ns = blockIdx.x & 7;           // 16-column n slice
    const float* W = (g == 0 ? Wi : g == 1 ? Wf : g == 2 ? Wz : Wo) + hh * HDn * HDn;
    char* dhi = (char*)&g_Wimg[g][hh][0][0];
    char* dlo = (char*)&g_Wimg[g][hh][1][0];
    for (int t = threadIdx.x; t < 16 * HDn; t += blockDim.x) {
        int n = (ns << 4) + (t >> 7);  // output col e
        int k = t & 127;               // input dim d
        float w = W[k * HDn + n];
        __nv_bfloat16 hi = __float2bfloat16_rn(w);
        float rem = w - __bfloat162float(hi);
        __nv_bfloat16 lo = __float2bfloat16_rn(rem);
        int phys = ((((k >> 3) ^ (n & 7)) << 4) | ((k & 7) << 1));
        *(__nv_bfloat16*)(dhi + n * 256 + phys) = hi;
        *(__nv_bfloat16*)(dlo + n * 256 + phys) = lo;
    }
}

// ---------------------------------------------------------------------------
// Fused sLSTM kernel. CTA = 64 rows x one head (128 cols). 16 warps: 4 row x
// 4 col, each warp m16 x n32. Split-bf16 mma.sync GEMM (3 passes) for all 4
// gates into registers; accumulators staged through smem; coalesced float4
// streaming epilogue.
// ---------------------------------------------------------------------------
__global__ void __launch_bounds__(THREADS, 1) slstm_main(
    const float* __restrict__ gi, const float* __restrict__ gf,
    const float* __restrict__ gz, const float* __restrict__ go,
    const float* __restrict__ gc, const float* __restrict__ gn,
    const float* __restrict__ gm, const float* __restrict__ gh,
    const float* __restrict__ b_i, const float* __restrict__ b_f,
    const float* __restrict__ b_z, const float* __restrict__ b_o,
    float* __restrict__ out) {
    extern __shared__ char smem[];
    const int tid = threadIdx.x;
    const int wid = tid >> 5;
    const int lane = tid & 31;
    const int head = blockIdx.x & 7;
    const int row0 = (blockIdx.x >> 3) << 6;   // 64-row tile
    const int wr = wid & 3;                    // warp row (16 rows)
    const int wc = wid >> 2;                   // warp col (32 cols)
    const uint32_t sb = smem_u32(smem);

    // --- A tile: load h, split bf16 hi/lo, swizzled store ---
    {
        const float* hsrc = gh + (size_t)row0 * Dn + head * HDn;
        for (int t = tid; t < 64 * 32; t += THREADS) {
            int row = t >> 5;
            int k4 = t & 31;                   // group of 4 floats
            float4 v = *(const float4*)(hsrc + (size_t)row * Dn + (k4 << 2));
            __nv_bfloat16 a0 = __float2bfloat16_rn(v.x);
            __nv_bfloat16 a1 = __float2bfloat16_rn(v.y);
            __nv_bfloat16 a2 = __float2bfloat16_rn(v.z);
            __nv_bfloat16 a3 = __float2bfloat16_rn(v.w);
            __nv_bfloat16 l0 = __float2bfloat16_rn(v.x - __bfloat162float(a0));
            __nv_bfloat16 l1 = __float2bfloat16_rn(v.y - __bfloat162float(a1));
            __nv_bfloat16 l2 = __float2bfloat16_rn(v.z - __bfloat162float(a2));
            __nv_bfloat16 l3 = __float2bfloat16_rn(v.w - __bfloat162float(a3));
            uint32_t hi01 = (uint32_t)__bfloat16_as_ushort(a0) | ((uint32_t)__bfloat16_as_ushort(a1) << 16);
            uint32_t hi23 = (uint32_t)__bfloat16_as_ushort(a2) | ((uint32_t)__bfloat16_as_ushort(a3) << 16);
            uint32_t lo01 = (uint32_t)__bfloat16_as_ushort(l0) | ((uint32_t)__bfloat16_as_ushort(l1) << 16);
            uint32_t lo23 = (uint32_t)__bfloat16_as_ushort(l2) | ((uint32_t)__bfloat16_as_ushort(l3) << 16);
            int phys = ((((k4 >> 1) ^ (row & 7)) << 4) | ((k4 & 1) << 3));
            *(uint2*)(smem + A_HI_OFF + row * 256 + phys) = make_uint2(hi01, hi23);
            *(uint2*)(smem + A_LO_OFF + row * 256 + phys) = make_uint2(lo01, lo23);
        }
    }
    // --- preload W gate 0 via cp.async (image pre-swizzled: linear copy) ---
    {
        const char* src = (const char*)&g_Wimg[0][head][0][0];
        uint32_t dst = sb + WBUF_OFF;
        for (int t = tid; t < 4096; t += THREADS)
            CP_ASYNC16(dst + t * 16, src + t * 16);
        asm volatile("cp.async.commit_group;");
        asm volatile("cp.async.wait_group 0;");
    }
    __syncthreads();

    float ac[4][16];   // [gate][ntile*4 + j]
#pragma unroll
    for (int g = 0; g < 4; ++g)
#pragma unroll
        for (int j = 0; j < 16; ++j) ac[g][j] = 0.0f;

    // Precomputed ldmatrix lane addressing (byte offsets, swizzle applied per kt)
    const int a_row = (wr << 4) + (lane & 15);
    const int a_half = lane >> 4;                         // k half (8 elems)
    const int b_n0 = (wc << 5) + (lane & 7) + ((lane >> 4) << 3);
    const int b_half = (lane >> 3) & 1;

#pragma unroll
    for (int g = 0; g < 4; ++g) {
        const uint32_t wb = sb + WBUF_OFF + (uint32_t)(g & 1) * 65536u;
        if (g < 3) {
            const char* src = (const char*)&g_Wimg[g + 1][head][0][0];
            uint32_t dst = sb + WBUF_OFF + (uint32_t)((g + 1) & 1) * 65536u;
            for (int t = tid; t < 4096; t += THREADS)
                CP_ASYNC16(dst + t * 16, src + t * 16);
            asm volatile("cp.async.commit_group;");
        }
#pragma unroll
        for (int p = 0; p < 3; ++p) {
            const uint32_t abase = sb + ((p == 2) ? A_LO_OFF : A_HI_OFF) + a_row * 256;
            const uint32_t bbase = wb + ((p == 1) ? 32768u : 0u);
#pragma unroll
            for (int kt = 0; kt < 8; ++kt) {
                uint32_t a0, a1, a2, a3;
                {
                    int chunk = (kt << 1) + a_half;
                    uint32_t aaddr = abase + (((chunk ^ (a_row & 7)) & 15) << 4);
                    LDMX4(a0, a1, a2, a3, aaddr);
                }
                uint32_t b0, b1, b2, b3, b4, b5, b6, b7;
                {
                    int chunk = (kt << 1) + b_half;
                    int n0 = b_n0;
                    uint32_t baddr0 = bbase + n0 * 256 + (((chunk ^ (n0 & 7)) & 15) << 4);
                    int n1 = b_n0 + 16;
                    uint32_t baddr1 = bbase + n1 * 256 + (((chunk ^ (n1 & 7)) & 15) << 4);
                    LDMX4(b0, b1, b2, b3, baddr0);
                    LDMX4(b4, b5, b6, b7, baddr1);
                }
                MMA_BF16(ac[g] + 0,  a0, a1, a2, a3, b0, b1);
                MMA_BF16(ac[g] + 4,  a0, a1, a2, a3, b2, b3);
                MMA_BF16(ac[g] + 8,  a0, a1, a2, a3, b4, b5);
                MMA_BF16(ac[g] + 12, a0, a1, a2, a3, b6, b7);
            }
        }
        if (g < 3) {
            asm volatile("cp.async.wait_group 0;");
            __syncthreads();
        }
    }

    // --- redistribute accumulators through smem (frees fragment layout) ---
    __syncthreads();   // all warps done reading A/W smem
    {
        float* pre = (float*)smem;
        const int g0 = lane >> 2;
        const int cq = lane & 3;
#pragma unroll
        for (int g = 0; g < 4; ++g) {
#pragma unroll
            for (int rs = 0; rs < 2; ++rs) {
                const int rl = (wr << 4) + g0 + (rs << 3);
                float* dst = pre + ((g << 6) + rl) * PRE_STRIDE + (wc << 5) + (cq << 1);
#pragma unroll
                for (int nt = 0; nt < 4; ++nt) {
                    *(float2*)(dst + (nt << 3)) =
                        make_float2(ac[g][nt * 4 + rs * 2], ac[g][nt * 4 + rs * 2 + 1]);
                }
            }
        }
    }
    __syncthreads();

    // --- coalesced streaming epilogue: thread -> (row, 4 consecutive cols) ---
    {
        const float* pre = (const float*)smem;
        const int erow = tid >> 5;            // 0..15 (row within 16-row pass)
        const int ecol = (tid & 31) << 2;     // 0..124
        const int gcol = head * HDn + ecol;
        const float4 vbi = *(const float4*)(b_i + gcol);
        const float4 vbf = *(const float4*)(b_f + gcol);
        const float4 vbz = *(const float4*)(b_z + gcol);
        const float4 vbo = *(const float4*)(b_o + gcol);
#pragma unroll
        for (int p = 0; p < 4; ++p) {
            const int row = (p << 4) + erow;
            const size_t idx = (size_t)(row0 + row) * Dn + gcol;
            const float4 vi = __ldcs((const float4*)(gi + idx));
            const float4 vf = __ldcs((const float4*)(gf + idx));
            const float4 vz = __ldcs((const float4*)(gz + idx));
            const float4 vo = __ldcs((const float4*)(go + idx));
            const float4 vc = __ldcs((const float4*)(gc + idx));
            const float4 vn = __ldcs((const float4*)(gn + idx));
            const float4 vm = __ldcs((const float4*)(gm + idx));
            const float4 pi = *(const float4*)(pre + ((0 << 6) + row) * PRE_STRIDE + ecol);
            const float4 pf = *(const float4*)(pre + ((1 << 6) + row) * PRE_STRIDE + ecol);
            const float4 pz = *(const float4*)(pre + ((2 << 6) + row) * PRE_STRIDE + ecol);
            const float4 po = *(const float4*)(pre + ((3 << 6) + row) * PRE_STRIDE + ecol);
            float4 oc, on, om, oh;
            const float* pvi = (const float*)&vi;  const float* pvf = (const float*)&vf;
            const float* pvz = (const float*)&vz;  const float* pvo = (const float*)&vo;
            const float* pvc = (const float*)&vc;  const float* pvn = (const float*)&vn;
            const float* pvm = (const float*)&vm;
            const float* ppi = (const float*)&pi;  const float* ppf = (const float*)&pf;
            const float* ppz = (const float*)&pz;  const float* ppo = (const float*)&po;
            const float* pbi = (const float*)&vbi; const float* pbf = (const float*)&vbf;
            const float* pbz = (const float*)&vbz; const float* pbo = (const float*)&vbo;
            float* poc = (float*)&oc; float* pon = (float*)&on;
            float* pom = (float*)&om; float* poh = (float*)&oh;
#pragma unroll
            for (int e = 0; e < 4; ++e) {
                const float ip = pvi[e] + ppi[e] + pbi[e];
                const float fp = pvf[e] + ppf[e] + pbf[e];
                const float zp = pvz[e] + ppz[e] + pbz[e];
                const float op = pvo[e] + ppo[e] + pbo[e];
                const float cv = pvc[e];
                const float nv = pvn[e];
                const float mv = pvm[e];
                const float osig = __fdividef(1.0f, 1.0f + __expf(-op));
                const float lf = fminf(fp, 0.0f) - __logf(1.0f + __expf(-fabsf(fp)));
                const float mn = fmaxf(lf + mv, ip);
                const float i_p = fminf(__expf(ip - mn), 1.0f);
                const float f_p = fminf(__expf(lf + mv - mn), 1.0f);
                const float cn = f_p * cv + i_p * tanhf(zp);
                const float nn = f_p * nv + i_p;
                const float hn = osig * __fdividef(cn, fmaxf(nn, 1e-6f));
                poc[e] = cn; pon[e] = nn; pom[e] = mn; poh[e] = hn;
            }
            __stcs((float4*)(out + idx), oc);
            __stcs((float4*)(out + BDsz + idx), on);
            __stcs((float4*)(out + 2 * BDsz + idx), om);
            __stcs((float4*)(out + 3 * BDsz + idx), oh);
        }
    }
}

extern "C" void kernel_launch(void* const* d_in, const int* in_sizes, int n_in,
                              void* d_out, int out_size) {
    (void)in_sizes; (void)n_in; (void)out_size;
    // setup_inputs() dict insertion order: i, f, z, o, c, m, h, n, Wi, Wf, Wz, Wo, bi, bf, bz, bo
    const float* i_ = (const float*)d_in[0];
    const float* f_ = (const float*)d_in[1];
    const float* z_ = (const float*)d_in[2];
    const float* o_ = (const float*)d_in[3];
    const float* c_ = (const float*)d_in[4];
    const float* m_ = (const float*)d_in[5];
    const float* h_ = (const float*)d_in[6];
    const float* n_ = (const float*)d_in[7];
    const float* Wi = (const float*)d_in[8];
    const float* Wf = (const float*)d_in[9];
    const float* Wz = (const float*)d_in[10];
    const float* Wo = (const float*)d_in[11];
    const float* bi = (const float*)d_in[12];
    const float* bf = (const float*)d_in[13];
    const float* bz = (const float*)d_in[14];
    const float* bo = (const float*)d_in[15];
    float* out = (float*)d_out;

    cudaFuncSetAttribute(slstm_main, cudaFuncAttributeMaxDynamicSharedMemorySize, SMEM_TOTAL);

    prep_w_kernel<<<256, 256>>>(Wi, Wf, Wz, Wo);
    slstm_main<<<1024, THREADS, SMEM_TOTAL>>>(i_, f_, z_, o_, c_, n_, m_, h_,
                                              bi, bf, bz, bo, out);
}

// round 7
// speedup vs baseline: 1.3741x; 1.1381x over previous
#include <cuda_runtime.h>
#include <cuda_bf16.h>
#include <cstdint>
#include <math.h>

#define Bn   8192
#define Dn   1024
#define HDn  128
#define BDsz ((size_t)Bn * (size_t)Dn)

#define THREADS 512

// smem layout (bytes)
#define A_HI_OFF   0            // 64 rows x 256B = 16KB
#define A_LO_OFF   16384
#define WBUF_OFF   32768        // two 64KB W buffers (hi 32KB + lo 32KB each)
#define SMEM_TOTAL 163840
// After GEMM the whole smem is reused as the preact store:
// 4 gates x 64 rows x 132 floats (padded) = 135168 bytes < SMEM_TOTAL
#define PRE_STRIDE 132

// Pre-swizzled, transposed, hi/lo-split weight image: [gate][head][hi/lo][n=128][k=128]
// row = n (256 bytes of bf16 k), XOR-swizzled 16B chunks: phys_chunk = (k>>3) ^ (n&7)
__device__ __align__(16) __nv_bfloat16 g_Wimg[4][8][2][16384];

static __device__ __forceinline__ uint32_t smem_u32(const void* p) {
    uint32_t a;
    asm("{ .reg .u64 t; cvta.to.shared.u64 t, %1; cvt.u32.u64 %0, t; }" : "=r"(a) : "l"(p));
    return a;
}

#define LDMX4(r0, r1, r2, r3, addr)                                            \
    asm volatile("ldmatrix.sync.aligned.m8n8.x4.shared.b16 {%0,%1,%2,%3}, [%4];" \
                 : "=r"(r0), "=r"(r1), "=r"(r2), "=r"(r3) : "r"(addr))

#define MMA_BF16(d, a0, a1, a2, a3, b0, b1)                                    \
    asm volatile("mma.sync.aligned.m16n8k16.row.col.f32.bf16.bf16.f32 "        \
                 "{%0,%1,%2,%3},{%4,%5,%6,%7},{%8,%9},{%0,%1,%2,%3};"          \
                 : "+f"((d)[0]), "+f"((d)[1]), "+f"((d)[2]), "+f"((d)[3])      \
                 : "r"(a0), "r"(a1), "r"(a2), "r"(a3), "r"(b0), "r"(b1))

#define CP_ASYNC16(dst, src)                                                   \
    asm volatile("cp.async.cg.shared.global [%0], [%1], 16;" :: "r"(dst), "l"(src))

// ---------------------------------------------------------------------------
// Weight prep: W[h][d][e] (d=input, e=output) -> image[n=e][k=d], bf16 hi/lo
// split, XOR-swizzled 16B chunks within each 256B row. 256 CTAs (n-sliced).
// ---------------------------------------------------------------------------
__global__ void prep_w_kernel(const float* __restrict__ Wi, const float* __restrict__ Wf,
                              const float* __restrict__ Wz, const float* __restrict__ Wo) {
    int g  = blockIdx.x >> 6;
    int hh = (blockIdx.x >> 3) & 7;
    int ns = blockIdx.x & 7;           // 16-column n slice
    const float* W = (g == 0 ? Wi : g == 1 ? Wf : g == 2 ? Wz : Wo) + hh * HDn * HDn;
    char* dhi = (char*)&g_Wimg[g][hh][0][0];
    char* dlo = (char*)&g_Wimg[g][hh][1][0];
    for (int t = threadIdx.x; t < 16 * HDn; t += blockDim.x) {
        int n = (ns << 4) + (t >> 7);  // output col e
        int k = t & 127;               // input dim d
        float w = W[k * HDn + n];
        __nv_bfloat16 hi = __float2bfloat16_rn(w);
        float rem = w - __bfloat162float(hi);
        __nv_bfloat16 lo = __float2bfloat16_rn(rem);
        int phys = ((((k >> 3) ^ (n & 7)) << 4) | ((k & 7) << 1));
        *(__nv_bfloat16*)(dhi + n * 256 + phys) = hi;
        *(__nv_bfloat16*)(dlo + n * 256 + phys) = lo;
    }
}

// ---------------------------------------------------------------------------
// Fused sLSTM kernel. CTA = 64 rows x one head (128 cols). 16 warps: 4 row x
// 4 col, each warp m16 x n32. Split-bf16 mma.sync GEMM (3 logical passes with
// fragment reuse: 6 ldmatrix per gate-kt) for all 4 gates into registers;
// accumulators staged through smem; coalesced float4 streaming epilogue.
// ---------------------------------------------------------------------------
__global__ void __launch_bounds__(THREADS, 1) slstm_main(
    const float* __restrict__ gi, const float* __restrict__ gf,
    const float* __restrict__ gz, const float* __restrict__ go,
    const float* __restrict__ gc, const float* __restrict__ gn,
    const float* __restrict__ gm, const float* __restrict__ gh,
    const float* __restrict__ b_i, const float* __restrict__ b_f,
    const float* __restrict__ b_z, const float* __restrict__ b_o,
    float* __restrict__ out) {
    extern __shared__ char smem[];
    const int tid = threadIdx.x;
    const int wid = tid >> 5;
    const int lane = tid & 31;
    const int head = blockIdx.x & 7;
    const int row0 = (blockIdx.x >> 3) << 6;   // 64-row tile
    const int wr = wid & 3;                    // warp row (16 rows)
    const int wc = wid >> 2;                   // warp col (32 cols)
    const uint32_t sb = smem_u32(smem);

    // --- A tile: load h, split bf16 hi/lo, swizzled store ---
    {
        const float* hsrc = gh + (size_t)row0 * Dn + head * HDn;
        for (int t = tid; t < 64 * 32; t += THREADS) {
            int row = t >> 5;
            int k4 = t & 31;                   // group of 4 floats
            float4 v = *(const float4*)(hsrc + (size_t)row * Dn + (k4 << 2));
            __nv_bfloat16 a0 = __float2bfloat16_rn(v.x);
            __nv_bfloat16 a1 = __float2bfloat16_rn(v.y);
            __nv_bfloat16 a2 = __float2bfloat16_rn(v.z);
            __nv_bfloat16 a3 = __float2bfloat16_rn(v.w);
            __nv_bfloat16 l0 = __float2bfloat16_rn(v.x - __bfloat162float(a0));
            __nv_bfloat16 l1 = __float2bfloat16_rn(v.y - __bfloat162float(a1));
            __nv_bfloat16 l2 = __float2bfloat16_rn(v.z - __bfloat162float(a2));
            __nv_bfloat16 l3 = __float2bfloat16_rn(v.w - __bfloat162float(a3));
            uint32_t hi01 = (uint32_t)__bfloat16_as_ushort(a0) | ((uint32_t)__bfloat16_as_ushort(a1) << 16);
            uint32_t hi23 = (uint32_t)__bfloat16_as_ushort(a2) | ((uint32_t)__bfloat16_as_ushort(a3) << 16);
            uint32_t lo01 = (uint32_t)__bfloat16_as_ushort(l0) | ((uint32_t)__bfloat16_as_ushort(l1) << 16);
            uint32_t lo23 = (uint32_t)__bfloat16_as_ushort(l2) | ((uint32_t)__bfloat16_as_ushort(l3) << 16);
            int phys = ((((k4 >> 1) ^ (row & 7)) << 4) | ((k4 & 1) << 3));
            *(uint2*)(smem + A_HI_OFF + row * 256 + phys) = make_uint2(hi01, hi23);
            *(uint2*)(smem + A_LO_OFF + row * 256 + phys) = make_uint2(lo01, lo23);
        }
    }
    // --- preload W gate 0 via cp.async (image pre-swizzled: linear copy) ---
    {
        const char* src = (const char*)&g_Wimg[0][head][0][0];
        uint32_t dst = sb + WBUF_OFF;
        for (int t = tid; t < 4096; t += THREADS)
            CP_ASYNC16(dst + t * 16, src + t * 16);
        asm volatile("cp.async.commit_group;");
        asm volatile("cp.async.wait_group 0;");
    }
    __syncthreads();

    float ac[4][16];   // [gate][ntile*4 + j]
#pragma unroll
    for (int g = 0; g < 4; ++g)
#pragma unroll
        for (int j = 0; j < 16; ++j) ac[g][j] = 0.0f;

    // Precomputed ldmatrix lane addressing (byte offsets, swizzle applied per kt)
    const int a_row = (wr << 4) + (lane & 15);
    const int a_half = lane >> 4;                         // k half (8 elems)
    const int b_n0 = (wc << 5) + (lane & 7) + ((lane >> 4) << 3);
    const int b_half = (lane >> 3) & 1;

#pragma unroll
    for (int g = 0; g < 4; ++g) {
        const uint32_t wb = sb + WBUF_OFF + (uint32_t)(g & 1) * 65536u;
        if (g < 3) {
            const char* src = (const char*)&g_Wimg[g + 1][head][0][0];
            uint32_t dst = sb + WBUF_OFF + (uint32_t)((g + 1) & 1) * 65536u;
            for (int t = tid; t < 4096; t += THREADS)
                CP_ASYNC16(dst + t * 16, src + t * 16);
            asm volatile("cp.async.commit_group;");
        }
        // Fragment-reuse inner loop: per kt load Bhi,Blo,Ahi -> 8 MMAs,
        // then Alo (reusing A regs) -> 4 MMAs. 6 ldmatrix/kt instead of 9.
#pragma unroll
        for (int kt = 0; kt < 8; ++kt) {
            // B fragments (hi and lo)
            uint32_t bh0, bh1, bh2, bh3, bh4, bh5, bh6, bh7;
            uint32_t bl0, bl1, bl2, bl3, bl4, bl5, bl6, bl7;
            {
                int chunk = (kt << 1) + b_half;
                int n0 = b_n0;
                int n1 = b_n0 + 16;
                uint32_t off0 = (uint32_t)(n0 * 256 + (((chunk ^ (n0 & 7)) & 15) << 4));
                uint32_t off1 = (uint32_t)(n1 * 256 + (((chunk ^ (n1 & 7)) & 15) << 4));
                LDMX4(bh0, bh1, bh2, bh3, wb + off0);
                LDMX4(bh4, bh5, bh6, bh7, wb + off1);
                LDMX4(bl0, bl1, bl2, bl3, wb + 32768u + off0);
                LDMX4(bl4, bl5, bl6, bl7, wb + 32768u + off1);
            }
            // A fragment offset for this kt
            uint32_t aoff;
            {
                int chunk = (kt << 1) + a_half;
                aoff = (uint32_t)(a_row * 256 + (((chunk ^ (a_row & 7)) & 15) << 4));
            }
            uint32_t a0, a1, a2, a3;
            LDMX4(a0, a1, a2, a3, sb + A_HI_OFF + aoff);
            // A-hi x B-hi
            MMA_BF16(ac[g] + 0,  a0, a1, a2, a3, bh0, bh1);
            MMA_BF16(ac[g] + 4,  a0, a1, a2, a3, bh2, bh3);
            MMA_BF16(ac[g] + 8,  a0, a1, a2, a3, bh4, bh5);
            MMA_BF16(ac[g] + 12, a0, a1, a2, a3, bh6, bh7);
            // A-hi x B-lo
            MMA_BF16(ac[g] + 0,  a0, a1, a2, a3, bl0, bl1);
            MMA_BF16(ac[g] + 4,  a0, a1, a2, a3, bl2, bl3);
            MMA_BF16(ac[g] + 8,  a0, a1, a2, a3, bl4, bl5);
            MMA_BF16(ac[g] + 12, a0, a1, a2, a3, bl6, bl7);
            // A-lo x B-hi (reuse A registers)
            LDMX4(a0, a1, a2, a3, sb + A_LO_OFF + aoff);
            MMA_BF16(ac[g] + 0,  a0, a1, a2, a3, bh0, bh1);
            MMA_BF16(ac[g] + 4,  a0, a1, a2, a3, bh2, bh3);
            MMA_BF16(ac[g] + 8,  a0, a1, a2, a3, bh4, bh5);
            MMA_BF16(ac[g] + 12, a0, a1, a2, a3, bh6, bh7);
        }
        if (g < 3) {
            asm volatile("cp.async.wait_group 0;");
            __syncthreads();
        }
    }

    // --- redistribute accumulators through smem (frees fragment layout) ---
    __syncthreads();   // all warps done reading A/W smem
    {
        float* pre = (float*)smem;
        const int g0 = lane >> 2;
        const int cq = lane & 3;
#pragma unroll
        for (int g = 0; g < 4; ++g) {
#pragma unroll
            for (int rs = 0; rs < 2; ++rs) {
                const int rl = (wr << 4) + g0 + (rs << 3);
                float* dst = pre + ((g << 6) + rl) * PRE_STRIDE + (wc << 5) + (cq << 1);
#pragma unroll
                for (int nt = 0; nt < 4; ++nt) {
                    *(float2*)(dst + (nt << 3)) =
                        make_float2(ac[g][nt * 4 + rs * 2], ac[g][nt * 4 + rs * 2 + 1]);
                }
            }
        }
    }
    __syncthreads();

    // --- coalesced streaming epilogue: thread -> (row, 4 consecutive cols) ---
    {
        const float* pre = (const float*)smem;
        const int erow = tid >> 5;            // 0..15 (row within 16-row pass)
        const int ecol = (tid & 31) << 2;     // 0..124
        const int gcol = head * HDn + ecol;
        const float4 vbi = *(const float4*)(b_i + gcol);
        const float4 vbf = *(const float4*)(b_f + gcol);
        const float4 vbz = *(const float4*)(b_z + gcol);
        const float4 vbo = *(const float4*)(b_o + gcol);
#pragma unroll
        for (int p = 0; p < 4; ++p) {
            const int row = (p << 4) + erow;
            const size_t idx = (size_t)(row0 + row) * Dn + gcol;
            const float4 vi = __ldcs((const float4*)(gi + idx));
            const float4 vf = __ldcs((const float4*)(gf + idx));
            const float4 vz = __ldcs((const float4*)(gz + idx));
            const float4 vo = __ldcs((const float4*)(go + idx));
            const float4 vc = __ldcs((const float4*)(gc + idx));
            const float4 vn = __ldcs((const float4*)(gn + idx));
            const float4 vm = __ldcs((const float4*)(gm + idx));
            const float4 pi = *(const float4*)(pre + ((0 << 6) + row) * PRE_STRIDE + ecol);
            const float4 pf = *(const float4*)(pre + ((1 << 6) + row) * PRE_STRIDE + ecol);
            const float4 pz = *(const float4*)(pre + ((2 << 6) + row) * PRE_STRIDE + ecol);
            const float4 po = *(const float4*)(pre + ((3 << 6) + row) * PRE_STRIDE + ecol);
            float4 oc, on, om, oh;
            const float* pvi = (const float*)&vi;  const float* pvf = (const float*)&vf;
            const float* pvz = (const float*)&vz;  const float* pvo = (const float*)&vo;
            const float* pvc = (const float*)&vc;  const float* pvn = (const float*)&vn;
            const float* pvm = (const float*)&vm;
            const float* ppi = (const float*)&pi;  const float* ppf = (const float*)&pf;
            const float* ppz = (const float*)&pz;  const float* ppo = (const float*)&po;
            const float* pbi = (const float*)&vbi; const float* pbf = (const float*)&vbf;
            const float* pbz = (const float*)&vbz; const float* pbo = (const float*)&vbo;
            float* poc = (float*)&oc; float* pon = (float*)&on;
            float* pom = (float*)&om; float* poh = (float*)&oh;
#pragma unroll
            for (int e = 0; e < 4; ++e) {
                const float ip = pvi[e] + ppi[e] + pbi[e];
                const float fp = pvf[e] + ppf[e] + pbf[e];
                const float zp = pvz[e] + ppz[e] + pbz[e];
                const float op = pvo[e] + ppo[e] + pbo[e];
                const float cv = pvc[e];
                const float nv = pvn[e];
                const float mv = pvm[e];
                const float osig = __fdividef(1.0f, 1.0f + __expf(-op));
                const float lf = fminf(fp, 0.0f) - __logf(1.0f + __expf(-fabsf(fp)));
                const float mn = fmaxf(lf + mv, ip);
                const float i_p = fminf(__expf(ip - mn), 1.0f);
                const float f_p = fminf(__expf(lf + mv - mn), 1.0f);
                const float cn = f_p * cv + i_p * tanhf(zp);
                const float nn = f_p * nv + i_p;
                const float hn = osig * __fdividef(cn, fmaxf(nn, 1e-6f));
                poc[e] = cn; pon[e] = nn; pom[e] = mn; poh[e] = hn;
            }
            __stcs((float4*)(out + idx), oc);
            __stcs((float4*)(out + BDsz + idx), on);
            __stcs((float4*)(out + 2 * BDsz + idx), om);
            __stcs((float4*)(out + 3 * BDsz + idx), oh);
        }
    }
}

extern "C" void kernel_launch(void* const* d_in, const int* in_sizes, int n_in,
                              void* d_out, int out_size) {
    (void)in_sizes; (void)n_in; (void)out_size;
    // setup_inputs() dict insertion order: i, f, z, o, c, m, h, n, Wi, Wf, Wz, Wo, bi, bf, bz, bo
    const float* i_ = (const float*)d_in[0];
    const float* f_ = (const float*)d_in[1];
    const float* z_ = (const float*)d_in[2];
    const float* o_ = (const float*)d_in[3];
    const float* c_ = (const float*)d_in[4];
    const float* m_ = (const float*)d_in[5];
    const float* h_ = (const float*)d_in[6];
    const float* n_ = (const float*)d_in[7];
    const float* Wi = (const float*)d_in[8];
    const float* Wf = (const float*)d_in[9];
    const float* Wz = (const float*)d_in[10];
    const float* Wo = (const float*)d_in[11];
    const float* bi = (const float*)d_in[12];
    const float* bf = (const float*)d_in[13];
    const float* bz = (const float*)d_in[14];
    const float* bo = (const float*)d_in[15];
    float* out = (float*)d_out;

    cudaFuncSetAttribute(slstm_main, cudaFuncAttributeMaxDynamicSharedMemorySize, SMEM_TOTAL);

    prep_w_kernel<<<256, 256>>>(Wi, Wf, Wz, Wo);
    slstm_main<<<1024, THREADS, SMEM_TOTAL>>>(i_, f_, z_, o_, c_, n_, m_, h_,
                                              bi, bf, bz, bo, out);
}